// round 14
// baseline (speedup 1.0000x reference)
#include <cuda_runtime.h>
#include <cstdint>

#define DD 1024
#define NB 4
#define SQ 2048
#define ROWS (NB*SQ)            /* 8192 */
#define NELEM (ROWS*DD)         /* 8388608 */

// ---------------- scratch ----------------
__device__ float g_absmax[4];
__device__ float g_nx[NELEM];
__device__ float g_nx2[NELEM];
__device__ float g_qkv[ROWS*3*DD];
__device__ float g_attnpre[NELEM];
__device__ float g_hattn[NELEM];
__device__ float g_xbuf[NELEM];
__device__ float g_ff1[ROWS*4*DD];
__device__ float g_ff2[ROWS*4*DD];

// ---------------- helpers ----------------
__device__ __forceinline__ uint32_t packbf(float lo, float hi){
    uint32_t r; asm("cvt.rn.bf16x2.f32 %0, %1, %2;" : "=r"(r) : "f"(hi), "f"(lo));
    return r;
}
__device__ __forceinline__ float fexp(float x){
    float y = x * 1.4426950408889634f;
    y = fminf(fmaxf(y, -120.f), 120.f);
    float r = rintf(y);
    float f = y - r;
    float p = 1.f + f*(0.6931471805599453f + f*(0.2402265069591007f +
              f*(0.05550410866482158f + f*(0.009618129107628477f +
              f*0.0013333558146428443f))));
    return __int_as_float(__float_as_int(p) + (((int)r) << 23));
}
__device__ __forceinline__ void mma16(float (&d)[4], const uint32_t* a, uint32_t b0, uint32_t b1){
    asm volatile("mma.sync.aligned.m16n8k16.row.col.f32.bf16.bf16.f32 "
        "{%0,%1,%2,%3},{%4,%5,%6,%7},{%8,%9},{%0,%1,%2,%3};"
        : "+f"(d[0]),"+f"(d[1]),"+f"(d[2]),"+f"(d[3])
        : "r"(a[0]),"r"(a[1]),"r"(a[2]),"r"(a[3]),"r"(b0),"r"(b1));
}
__device__ __forceinline__ void bfsplit(float x, float y, uint32_t& hi, uint32_t& lo){
    hi = packbf(x, y);
    float e0 = __uint_as_float(hi << 16);
    float e1 = __uint_as_float(hi & 0xffff0000u);
    lo = packbf(x - e0, y - e1);
}

// ---------------- small kernels ----------------
__global__ void zero_absmax_kernel() {
    if (threadIdx.x < 4) g_absmax[threadIdx.x] = 0.f;
}

__global__ void __launch_bounds__(256) rmsnorm_kernel(
    const float* __restrict__ x, const float* __restrict__ w,
    float* __restrict__ out, int slot)
{
    __shared__ float red[256];
    int tid = threadIdx.x;
    size_t row = blockIdx.x;
    float4 xv = ((const float4*)(x + row*DD))[tid];
    float ss = xv.x*xv.x + xv.y*xv.y + xv.z*xv.z + xv.w*xv.w;
    red[tid] = ss;
    __syncthreads();
    #pragma unroll
    for (int s = 128; s > 0; s >>= 1) {
        if (tid < s) red[tid] += red[tid + s];
        __syncthreads();
    }
    float rinv = rsqrtf(red[0] * (1.f/1024.f) + 1e-6f);
    __syncthreads();
    float4 wv = ((const float4*)w)[tid];
    float4 o;
    o.x = wv.x * (xv.x * rinv);
    o.y = wv.y * (xv.y * rinv);
    o.z = wv.z * (xv.z * rinv);
    o.w = wv.w * (xv.w * rinv);
    ((float4*)(out + row*DD))[tid] = o;
    float am = fmaxf(fmaxf(fabsf(o.x), fabsf(o.y)), fmaxf(fabsf(o.z), fabsf(o.w)));
    red[tid] = am;
    __syncthreads();
    #pragma unroll
    for (int s = 128; s > 0; s >>= 1) {
        if (tid < s) red[tid] = fmaxf(red[tid], red[tid + s]);
        __syncthreads();
    }
    if (tid == 0) atomicMax((int*)&g_absmax[slot], __float_as_int(red[0]));
}

// quantize to int codes, pack pairs as bf16x2 (exact for |code|<=128)
__global__ void __launch_bounds__(256) quant_pack_kernel(
    const float* __restrict__ in, uint32_t* __restrict__ outp, int slot, int n4)
{
    float scale = g_absmax[slot] * (1.f/127.f) + 1e-8f;
    float qinv = 1.f / scale;
    int stride = gridDim.x * blockDim.x;
    for (int i = blockIdx.x*blockDim.x + threadIdx.x; i < n4; i += stride) {
        float4 v = ((const float4*)in)[i];
        float q0 = fminf(fmaxf(rintf(v.x * qinv), -128.f), 127.f);
        float q1 = fminf(fmaxf(rintf(v.y * qinv), -128.f), 127.f);
        float q2 = fminf(fmaxf(rintf(v.z * qinv), -128.f), 127.f);
        float q3 = fminf(fmaxf(rintf(v.w * qinv), -128.f), 127.f);
        uint2 o;
        o.x = packbf(q0, q1);
        o.y = packbf(q2, q3);
        ((uint2*)outp)[i] = o;
    }
}

__global__ void __launch_bounds__(256) gate_kernel(
    float* __restrict__ a, const float* __restrict__ bsrc, int n4, int slot)
{
    __shared__ float red[256];
    float am = 0.f;
    int stride = gridDim.x * blockDim.x;
    for (int i = blockIdx.x*blockDim.x + threadIdx.x; i < n4; i += stride) {
        float4 u = ((const float4*)a)[i];
        float4 v = ((const float4*)bsrc)[i];
        float4 g;
        g.x = u.x / (1.f + fexp(-u.x)) * v.x;
        g.y = u.y / (1.f + fexp(-u.y)) * v.y;
        g.z = u.z / (1.f + fexp(-u.z)) * v.z;
        g.w = u.w / (1.f + fexp(-u.w)) * v.w;
        ((float4*)a)[i] = g;
        am = fmaxf(am, fmaxf(fmaxf(fabsf(g.x), fabsf(g.y)), fmaxf(fabsf(g.z), fabsf(g.w))));
    }
    red[threadIdx.x] = am;
    __syncthreads();
    #pragma unroll
    for (int s = 128; s > 0; s >>= 1) {
        if (threadIdx.x < s) red[threadIdx.x] = fmaxf(red[threadIdx.x], red[threadIdx.x + s]);
        __syncthreads();
    }
    if (threadIdx.x == 0) atomicMax((int*)&g_absmax[slot], __float_as_int(red[0]));
}

__global__ void __launch_bounds__(256) conv_combine_kernel(
    const float* __restrict__ x, const float* __restrict__ hrec,
    const float* __restrict__ hattn, const float* __restrict__ nx,
    const float* __restrict__ conv_w, const float* __restrict__ conv_b,
    float* __restrict__ xout)
{
    int bs = blockIdx.x;
    int b = bs >> 11;
    int s = bs & 2047;
    size_t rowbase = (size_t)bs * DD;
    for (int d = threadIdx.x; d < DD; d += 256) {
        float acc = conv_b[d];
        #pragma unroll
        for (int t = 0; t < 5; t++) {
            int ssi = s + t - 2;
            if (ssi >= 0 && ssi < SQ)
                acc = fmaf(nx[((size_t)b*SQ + ssi)*DD + d], conv_w[d*5 + t], acc);
        }
        size_t idx = rowbase + d;
        xout[idx] = x[idx] + hrec[idx] + hattn[idx] + acc;
    }
}

#define KC 32
#define SROWQ 20
#define TILEQ (128*SROWQ)   /* 2560 b32 units per tile */

// ================= bf16x3 GEMM, fp32 A & W (qkv, out-proj): 256 thr, 1 CTA/SM =================
__global__ void __launch_bounds__(256) mma_gemm_b3(
    const float* __restrict__ A, const float* __restrict__ W,
    const float* __restrict__ bias, float* __restrict__ C,
    int M, int N, int K)
{
    extern __shared__ uint32_t smem_u[];
    const int NT = 4;

    int tid = threadIdx.x;
    int wid = tid >> 5, lane = tid & 31;
    int wm = (wid & 1) * 64;
    int wn = (wid >> 1) * 32;
    int m0 = blockIdx.y * 128, n0 = blockIdx.x * 128;
    int lrow = tid >> 3, lc4 = (tid & 7) * 4;
    int g = lane >> 2, t4 = lane & 3;

    float d[4][4][4];
    #pragma unroll
    for (int i = 0; i < 4; i++)
        #pragma unroll
        for (int j = 0; j < 4; j++)
            #pragma unroll
            for (int q = 0; q < 4; q++) d[i][j][q] = 0.f;

    float4 av[4], wv[4];
    auto LDG = [&](int t){
        int k0 = t*KC + lc4;
        #pragma unroll
        for (int h = 0; h < 4; h++) {
            av[h] = *(const float4*)(A + (size_t)(m0 + lrow + h*32)*K + k0);
            wv[h] = *(const float4*)(W + (size_t)(n0 + lrow + h*32)*K + k0);
        }
    };
    auto STS = [&](int s){
        uint32_t* bufAh = smem_u + (size_t)s*NT*TILEQ;
        uint32_t* bufAl = bufAh + TILEQ;
        uint32_t* bufBh = bufAh + 2*TILEQ;
        uint32_t* bufBl = bufBh + TILEQ;
        #pragma unroll
        for (int h = 0; h < 4; h++) {
            int u0 = (lrow + h*32)*SROWQ + (tid & 7)*2;
            uint32_t h0, l0, h1, l1;
            bfsplit(av[h].x, av[h].y, h0, l0);
            bfsplit(av[h].z, av[h].w, h1, l1);
            bufAh[u0] = h0; bufAh[u0 + 1] = h1;
            bufAl[u0] = l0; bufAl[u0 + 1] = l1;
            bfsplit(wv[h].x, wv[h].y, h0, l0);
            bfsplit(wv[h].z, wv[h].w, h1, l1);
            bufBh[u0] = h0; bufBh[u0 + 1] = h1;
            bufBl[u0] = l0; bufBl[u0 + 1] = l1;
        }
    };

    const int T = K / KC;
    LDG(0); STS(0);
    if (T > 1) LDG(1);
    __syncthreads();

    for (int t = 0; t < T; t++) {
        const uint32_t* buf = smem_u + (size_t)(t & 1)*NT*TILEQ;
        const uint32_t* Ah  = buf;
        const uint32_t* Al  = buf + TILEQ;
        const uint32_t* Bh  = buf + 2*TILEQ;
        const uint32_t* Bl  = buf + 3*TILEQ;

        #pragma unroll
        for (int ks = 0; ks < 2; ks++) {
            int ku = ks*8;
            uint32_t ah[4][4], al[4][4];
            #pragma unroll
            for (int i = 0; i < 4; i++) {
                const uint32_t* base = Ah + (wm + i*16 + g)*SROWQ + ku + t4;
                ah[i][0] = base[0];
                ah[i][1] = base[8*SROWQ];
                ah[i][2] = base[4];
                ah[i][3] = base[8*SROWQ + 4];
                const uint32_t* b2 = Al + (wm + i*16 + g)*SROWQ + ku + t4;
                al[i][0] = b2[0];
                al[i][1] = b2[8*SROWQ];
                al[i][2] = b2[4];
                al[i][3] = b2[8*SROWQ + 4];
            }
            uint32_t bh[4][2], bl[4][2];
            #pragma unroll
            for (int j = 0; j < 4; j++) {
                const uint32_t* bb = Bh + (wn + j*8 + g)*SROWQ + ku + t4;
                bh[j][0] = bb[0]; bh[j][1] = bb[4];
                const uint32_t* bb2 = Bl + (wn + j*8 + g)*SROWQ + ku + t4;
                bl[j][0] = bb2[0]; bl[j][1] = bb2[4];
            }
            #pragma unroll
            for (int i = 0; i < 4; i++)
                #pragma unroll
                for (int j = 0; j < 4; j++) {
                    mma16(d[i][j], ah[i], bh[j][0], bh[j][1]);
                    mma16(d[i][j], al[i], bh[j][0], bh[j][1]);
                    mma16(d[i][j], ah[i], bl[j][0], bl[j][1]);
                }
        }

        if (t + 1 < T) {
            STS((t + 1) & 1);
            if (t + 2 < T) LDG(t + 2);
        }
        __syncthreads();
    }

    int r = lane >> 2, c2 = (lane & 3) * 2;
    #pragma unroll
    for (int j = 0; j < 4; j++) {
        int cc = n0 + wn + j*8 + c2;
        float b0 = bias[cc], b1 = bias[cc + 1];
        #pragma unroll
        for (int i = 0; i < 4; i++) {
            int r0 = m0 + wm + i*16 + r;
            #pragma unroll
            for (int half = 0; half < 2; half++) {
                int rr = r0 + half*8;
                size_t idx = (size_t)rr*N + cc;
                float2 o;
                o.x = d[i][j][half*2 + 0] + b0;
                o.y = d[i][j][half*2 + 1] + b1;
                *(float2*)(C + idx) = o;
            }
        }
    }
}

// ================= bf16x2 GEMM (packed codes A): 256 threads, 2 CTA/SM =================
// A is pre-packed bf16x2 codes, stride K/2 u32 per row.
// EPI 0: v.  EPI 1: tanh(v + exp(e2[n])*e1[m,n]).  EPI 2: v + e1[m,n].
template<int EPI>
__global__ void __launch_bounds__(256, 2) mma_gemm_q(
    const uint32_t* __restrict__ Aq, const float* __restrict__ W,
    const float* __restrict__ bias, float* __restrict__ C,
    int M, int N, int K,
    const float* __restrict__ e1, const float* __restrict__ e2, int slot)
{
    extern __shared__ uint32_t smem_u[];
    const int NT = 3;

    int tid = threadIdx.x;
    int wid = tid >> 5, lane = tid & 31;
    int wm = (wid & 1) * 64;
    int wn = (wid >> 1) * 32;
    int m0 = blockIdx.y * 128, n0 = blockIdx.x * 128;
    int lrow = tid >> 3, lc4 = (tid & 7) * 4;
    int g = lane >> 2, t4 = lane & 3;
    int Ku = K >> 1;   // u32 per A row

    float d[4][4][4];
    #pragma unroll
    for (int i = 0; i < 4; i++)
        #pragma unroll
        for (int j = 0; j < 4; j++)
            #pragma unroll
            for (int q = 0; q < 4; q++) d[i][j][q] = 0.f;

    uint2 av[4];
    float4 wv[4];
    auto LDG = [&](int t){
        int k0 = t*KC + lc4;
        int k0u = t*(KC/2) + (tid & 7)*2;
        #pragma unroll
        for (int h = 0; h < 4; h++) {
            av[h] = *(const uint2*)(Aq + (size_t)(m0 + lrow + h*32)*Ku + k0u);
            wv[h] = *(const float4*)(W + (size_t)(n0 + lrow + h*32)*K + k0);
        }
    };
    auto STS = [&](int s){
        uint32_t* bufAh = smem_u + (size_t)s*NT*TILEQ;
        uint32_t* bufBh = bufAh + TILEQ;
        uint32_t* bufBl = bufBh + TILEQ;
        #pragma unroll
        for (int h = 0; h < 4; h++) {
            int u0 = (lrow + h*32)*SROWQ + (tid & 7)*2;
            bufAh[u0]     = av[h].x;
            bufAh[u0 + 1] = av[h].y;
            uint32_t h0, l0, h1, l1;
            bfsplit(wv[h].x, wv[h].y, h0, l0);
            bfsplit(wv[h].z, wv[h].w, h1, l1);
            bufBh[u0] = h0; bufBh[u0 + 1] = h1;
            bufBl[u0] = l0; bufBl[u0 + 1] = l1;
        }
    };

    const int T = K / KC;
    LDG(0); STS(0);
    if (T > 1) LDG(1);
    __syncthreads();

    for (int t = 0; t < T; t++) {
        const uint32_t* buf = smem_u + (size_t)(t & 1)*NT*TILEQ;
        const uint32_t* Ah  = buf;
        const uint32_t* Bh  = buf + TILEQ;
        const uint32_t* Bl  = buf + 2*TILEQ;

        #pragma unroll
        for (int ks = 0; ks < 2; ks++) {
            int ku = ks*8;
            uint32_t ah[4][4];
            #pragma unroll
            for (int i = 0; i < 4; i++) {
                const uint32_t* base = Ah + (wm + i*16 + g)*SROWQ + ku + t4;
                ah[i][0] = base[0];
                ah[i][1] = base[8*SROWQ];
                ah[i][2] = base[4];
                ah[i][3] = base[8*SROWQ + 4];
            }
            uint32_t bh[4][2], bl[4][2];
            #pragma unroll
            for (int j = 0; j < 4; j++) {
                const uint32_t* bb = Bh + (wn + j*8 + g)*SROWQ + ku + t4;
                bh[j][0] = bb[0]; bh[j][1] = bb[4];
                const uint32_t* bb2 = Bl + (wn + j*8 + g)*SROWQ + ku + t4;
                bl[j][0] = bb2[0]; bl[j][1] = bb2[4];
            }
            #pragma unroll
            for (int i = 0; i < 4; i++)
                #pragma unroll
                for (int j = 0; j < 4; j++) {
                    mma16(d[i][j], ah[i], bh[j][0], bh[j][1]);
                    mma16(d[i][j], ah[i], bl[j][0], bl[j][1]);
                }
        }

        if (t + 1 < T) {
            STS((t + 1) & 1);
            if (t + 2 < T) LDG(t + 2);
        }
        __syncthreads();
    }

    float alpha = g_absmax[slot] * (1.f/127.f) + 1e-8f;
    int r = lane >> 2, c2 = (lane & 3) * 2;

    #pragma unroll
    for (int j = 0; j < 4; j++) {
        int cc = n0 + wn + j*8 + c2;
        float b0 = bias[cc], b1 = bias[cc + 1];
        float dn0 = 0.f, dn1 = 0.f;
        if (EPI == 1) { dn0 = expf(e2[cc]); dn1 = expf(e2[cc + 1]); }
        #pragma unroll
        for (int i = 0; i < 4; i++) {
            int r0 = m0 + wm + i*16 + r;
            #pragma unroll
            for (int half = 0; half < 2; half++) {
                int rr = r0 + half*8;
                size_t idx = (size_t)rr*N + cc;
                float v0 = alpha * d[i][j][half*2 + 0] + b0;
                float v1 = alpha * d[i][j][half*2 + 1] + b1;
                if (EPI == 1) {
                    v0 = tanhf(v0 + dn0 * e1[idx]);
                    v1 = tanhf(v1 + dn1 * e1[idx + 1]);
                } else if (EPI == 2) {
                    v0 += e1[idx];
                    v1 += e1[idx + 1];
                }
                float2 o; o.x = v0; o.y = v1;
                *(float2*)(C + idx) = o;
            }
        }
    }
}

// ================= MMA flash attention (all-bf16x3, register-resident P) =================
#define SKB 36
#define SVT 36
#define SVS 68
#define OFF_KBL  2304
#define OFF_VTH  4608
#define OFF_VTL  6912
#define OFF_VST  9216
#define ATTN_SMEM (13568*4)

__global__ void __launch_bounds__(256, 2) attn_mma(
    const float* __restrict__ qkv, float* __restrict__ out)
{
    extern __shared__ uint32_t smem_a[];
    uint32_t* Kbh  = smem_a;
    uint32_t* Kbl  = smem_a + OFF_KBL;
    uint32_t* VThi = smem_a + OFF_VTH;
    uint32_t* VTlo = smem_a + OFF_VTL;
    float*    Vst  = (float*)(smem_a + OFF_VST);

    int tid = threadIdx.x, w = tid >> 5, lane = tid & 31;
    int g = lane >> 2, t = lane & 3;
    int q0 = blockIdx.x * 128, h = blockIdx.y, b = blockIdx.z;
    const float* base = qkv + (size_t)b*SQ*3072 + h*64;

    uint32_t qh[4][4], ql[4][4];
    {
        const float* Qb = base + (size_t)(q0 + w*16)*3072;
        #pragma unroll
        for (int ks = 0; ks < 4; ks++) {
            #pragma unroll
            for (int q = 0; q < 4; q++) {
                int row = (q & 1) ? (g + 8) : g;
                int col = ks*16 + 2*t + ((q & 2) ? 8 : 0);
                float2 v = *(const float2*)(Qb + (size_t)row*3072 + col);
                v.x *= 0.125f; v.y *= 0.125f;
                bfsplit(v.x, v.y, qh[ks][q], ql[ks][q]);
            }
        }
    }

    float o[8][4];
    #pragma unroll
    for (int j = 0; j < 8; j++)
        #pragma unroll
        for (int q = 0; q < 4; q++) o[j][q] = 0.f;
    float m0 = -1e30f, m1 = -1e30f, l0 = 0.f, l1 = 0.f;

    for (int kt = 0; kt < SQ/64; kt++) {
        __syncthreads();
        for (int i = tid; i < 1024; i += 256) {
            int row = i >> 4, c4 = (i & 15) * 4;
            const float* gp = base + (size_t)(kt*64 + row)*3072 + 1024 + c4;
            float4 kv = *(const float4*)gp;
            float4 vv = *(const float4*)(gp + 1024);
            uint32_t h0, lo0, h1, lo1;
            bfsplit(kv.x, kv.y, h0, lo0);
            bfsplit(kv.z, kv.w, h1, lo1);
            int u = row*SKB + (i & 15)*2;
            Kbh[u] = h0; Kbh[u + 1] = h1;
            Kbl[u] = lo0; Kbl[u + 1] = lo1;
            *(float4*)(Vst + row*SVS + c4) = vv;
        }
        __syncthreads();
        for (int i = tid; i < 1024; i += 256) {
            int kp = i & 31, dp = i >> 5;
            float2 v0 = *(const float2*)(Vst + (2*kp)*SVS + 2*dp);
            float2 v1 = *(const float2*)(Vst + (2*kp + 1)*SVS + 2*dp);
            uint32_t h0, l0x, h1, l1x;
            bfsplit(v0.x, v1.x, h0, l0x);
            bfsplit(v0.y, v1.y, h1, l1x);
            VThi[(2*dp)*SVT + kp]     = h0;
            VTlo[(2*dp)*SVT + kp]     = l0x;
            VThi[(2*dp + 1)*SVT + kp] = h1;
            VTlo[(2*dp + 1)*SVT + kp] = l1x;
        }
        __syncthreads();

        float s[8][4];
        #pragma unroll
        for (int j = 0; j < 8; j++)
            #pragma unroll
            for (int q = 0; q < 4; q++) s[j][q] = 0.f;

        #pragma unroll
        for (int j = 0; j < 8; j++) {
            #pragma unroll
            for (int ks = 0; ks < 4; ks++) {
                const uint32_t* kb  = Kbh + (j*8 + g)*SKB + ks*8 + t;
                const uint32_t* kb2 = Kbl + (j*8 + g)*SKB + ks*8 + t;
                uint32_t bh0 = kb[0],  bh1 = kb[4];
                uint32_t bl0 = kb2[0], bl1 = kb2[4];
                mma16(s[j], qh[ks], bh0, bh1);
                mma16(s[j], ql[ks], bh0, bh1);
                mma16(s[j], qh[ks], bl0, bl1);
            }
        }

        float mt0 = -1e30f, mt1 = -1e30f;
        #pragma unroll
        for (int j = 0; j < 8; j++) {
            mt0 = fmaxf(mt0, fmaxf(s[j][0], s[j][1]));
            mt1 = fmaxf(mt1, fmaxf(s[j][2], s[j][3]));
        }
        mt0 = fmaxf(mt0, __shfl_xor_sync(0xffffffffu, mt0, 1));
        mt0 = fmaxf(mt0, __shfl_xor_sync(0xffffffffu, mt0, 2));
        mt1 = fmaxf(mt1, __shfl_xor_sync(0xffffffffu, mt1, 1));
        mt1 = fmaxf(mt1, __shfl_xor_sync(0xffffffffu, mt1, 2));
        float m0n = fmaxf(m0, mt0), m1n = fmaxf(m1, mt1);
        float a0 = fexp(m0 - m0n), a1 = fexp(m1 - m1n);

        float rs0 = 0.f, rs1 = 0.f;
        #pragma unroll
        for (int j = 0; j < 8; j++) {
            s[j][0] = fexp(s[j][0] - m0n);
            s[j][1] = fexp(s[j][1] - m0n);
            s[j][2] = fexp(s[j][2] - m1n);
            s[j][3] = fexp(s[j][3] - m1n);
            rs0 += s[j][0] + s[j][1];
            rs1 += s[j][2] + s[j][3];
        }
        rs0 += __shfl_xor_sync(0xffffffffu, rs0, 1);
        rs0 += __shfl_xor_sync(0xffffffffu, rs0, 2);
        rs1 += __shfl_xor_sync(0xffffffffu, rs1, 1);
        rs1 += __shfl_xor_sync(0xffffffffu, rs1, 2);
        l0 = l0*a0 + rs0;
        l1 = l1*a1 + rs1;
        m0 = m0n; m1 = m1n;
        #pragma unroll
        for (int j = 0; j < 8; j++) {
            o[j][0] *= a0; o[j][1] *= a0; o[j][2] *= a1; o[j][3] *= a1;
        }

        #pragma unroll
        for (int kk = 0; kk < 4; kk++) {
            uint32_t ah[4], al[4];
            bfsplit(s[2*kk][0],     s[2*kk][1],     ah[0], al[0]);
            bfsplit(s[2*kk][2],     s[2*kk][3],     ah[1], al[1]);
            bfsplit(s[2*kk + 1][0], s[2*kk + 1][1], ah[2], al[2]);
            bfsplit(s[2*kk + 1][2], s[2*kk + 1][3], ah[3], al[3]);
            #pragma unroll
            for (int j = 0; j < 8; j++) {
                const uint32_t* vh = VThi + (j*8 + g)*SVT + kk*8 + t;
                const uint32_t* vl = VTlo + (j*8 + g)*SVT + kk*8 + t;
                uint32_t bh0 = vh[0], bh1 = vh[4];
                uint32_t bl0 = vl[0], bl1 = vl[4];
                mma16(o[j], ah, bh0, bh1);
                mma16(o[j], al, bh0, bh1);
                mma16(o[j], ah, bl0, bl1);
            }
        }
    }

    float inv0 = 1.f / l0, inv1 = 1.f / l1;
    int row0 = q0 + w*16 + g;
    #pragma unroll
    for (int j = 0; j < 8; j++) {
        int col = h*64 + j*8 + 2*t;
        *(float2*)(out + (size_t)(b*SQ + row0)*DD + col) =
            make_float2(o[j][0]*inv0, o[j][1]*inv0);
        *(float2*)(out + (size_t)(b*SQ + row0 + 8)*DD + col) =
            make_float2(o[j][2]*inv1, o[j][3]*inv1);
    }
}

// ---------------- launch ----------------
extern "C" void kernel_launch(void* const* d_in, const int* in_sizes, int n_in,
                              void* d_out, int out_size)
{
    const float* x         = (const float*)d_in[0];
    const float* h_prev    = (const float*)d_in[1];
    const float* norm1_w   = (const float*)d_in[2];
    const float* norm2_w   = (const float*)d_in[3];
    const float* decay     = (const float*)d_in[4];
    const float* rec_W     = (const float*)d_in[5];
    const float* rec_b     = (const float*)d_in[6];
    const float* in_proj_w = (const float*)d_in[7];
    const float* in_proj_b = (const float*)d_in[8];
    const float* out_w     = (const float*)d_in[9];
    const float* out_b     = (const float*)d_in[10];
    const float* conv_w    = (const float*)d_in[11];
    const float* conv_b    = (const float*)d_in[12];
    const float* w1_W      = (const float*)d_in[13];
    const float* w1_b      = (const float*)d_in[14];
    const float* w2_W      = (const float*)d_in[15];
    const float* w2_b      = (const float*)d_in[16];
    const float* w3_W      = (const float*)d_in[17];
    const float* w3_b      = (const float*)d_in[18];

    float* out_x    = (float*)d_out;
    float* out_hrec = out_x + NELEM;

    float *nx, *nx2, *qkv, *attnpre, *hattn, *xbuf, *ff1, *ff2;
    cudaGetSymbolAddress((void**)&nx,      g_nx);
    cudaGetSymbolAddress((void**)&nx2,     g_nx2);
    cudaGetSymbolAddress((void**)&qkv,     g_qkv);
    cudaGetSymbolAddress((void**)&attnpre, g_attnpre);
    cudaGetSymbolAddress((void**)&hattn,   g_hattn);
    cudaGetSymbolAddress((void**)&xbuf,    g_xbuf);
    cudaGetSymbolAddress((void**)&ff1,     g_ff1);
    cudaGetSymbolAddress((void**)&ff2,     g_ff2);

    const int SMB3 = 2*4*TILEQ*4;   // 81920 B
    const int SMQ  = 2*3*TILEQ*4;   // 61440 B
    cudaFuncSetAttribute(mma_gemm_b3,  cudaFuncAttributeMaxDynamicSharedMemorySize, SMB3);
    cudaFuncSetAttribute(mma_gemm_q<0>, cudaFuncAttributeMaxDynamicSharedMemorySize, SMQ);
    cudaFuncSetAttribute(mma_gemm_q<1>, cudaFuncAttributeMaxDynamicSharedMemorySize, SMQ);
    cudaFuncSetAttribute(mma_gemm_q<2>, cudaFuncAttributeMaxDynamicSharedMemorySize, SMQ);
    cudaFuncSetAttribute(attn_mma, cudaFuncAttributeMaxDynamicSharedMemorySize, ATTN_SMEM);

    zero_absmax_kernel<<<1, 32>>>();
    // nx = rmsnorm(x), absmax -> slot 0
    rmsnorm_kernel<<<ROWS, 256>>>(x, norm1_w, nx, 0);
    // packed codes of nx -> nx2
    quant_pack_kernel<<<2048, 256>>>(nx, (uint32_t*)nx2, 0, NELEM/4);
    // qkv = nx @ in_proj_w^T + b   (bf16x3)
    mma_gemm_b3<<<dim3(24, 64), 256, SMB3>>>(nx, in_proj_w, in_proj_b, qkv,
                                             ROWS, 3072, 1024);
    // h_rec = tanh(scale0*(codes @ rec_W^T) + rec_b + exp(decay)*h_prev)
    mma_gemm_q<1><<<dim3(8, 64), 256, SMQ>>>((const uint32_t*)nx2, rec_W, rec_b, out_hrec,
                                             ROWS, 1024, 1024, h_prev, decay, 0);
    // flash attention
    attn_mma<<<dim3(16, 16, 4), 256, ATTN_SMEM>>>(qkv, attnpre);
    // out projection (bf16x3)
    mma_gemm_b3<<<dim3(8, 64), 256, SMB3>>>(attnpre, out_w, out_b, hattn,
                                            ROWS, 1024, 1024);
    conv_combine_kernel<<<ROWS, 256>>>(x, out_hrec, hattn, nx, conv_w, conv_b, xbuf);
    // nx2 = rmsnorm(xbuf) fp32, absmax -> slot 1; packed codes -> nx (free now)
    rmsnorm_kernel<<<ROWS, 256>>>(xbuf, norm2_w, nx2, 1);
    quant_pack_kernel<<<2048, 256>>>(nx2, (uint32_t*)nx, 1, NELEM/4);
    // ff1/ff2 = codes @ w1/w2
    mma_gemm_q<0><<<dim3(32, 64), 256, SMQ>>>((const uint32_t*)nx, w1_W, w1_b, ff1,
                                              ROWS, 4096, 1024, nullptr, nullptr, 1);
    mma_gemm_q<0><<<dim3(32, 64), 256, SMQ>>>((const uint32_t*)nx, w2_W, w2_b, ff2,
                                              ROWS, 4096, 1024, nullptr, nullptr, 1);
    // ff1 = silu(ff1)*ff2 (fp32), absmax -> slot 2; packed codes -> ff2
    gate_kernel<<<4096, 256>>>(ff1, ff2, (ROWS*4096)/4, 2);
    quant_pack_kernel<<<4096, 256>>>(ff1, (uint32_t*)ff2, 2, (ROWS*4096)/4);
    // out_x = xbuf + scale2*(codes @ w3^T) + b3
    mma_gemm_q<2><<<dim3(8, 64), 256, SMQ>>>((const uint32_t*)ff2, w3_W, w3_b, out_x,
                                             ROWS, 1024, 4096, xbuf, nullptr, 2);
}

// round 15
// speedup vs baseline: 1.0641x; 1.0641x over previous
#include <cuda_runtime.h>
#include <cstdint>

#define DD 1024
#define NB 4
#define SQ 2048
#define ROWS (NB*SQ)            /* 8192 */
#define NELEM (ROWS*DD)         /* 8388608 */

// ---------------- scratch ----------------
__device__ float g_absmax[4];
__device__ float g_nx[NELEM];
__device__ float g_nx2[NELEM];
__device__ float g_qkv[ROWS*3*DD];
__device__ float g_attnpre[NELEM];
__device__ float g_hattn[NELEM];
__device__ float g_xbuf[NELEM];
__device__ float g_ff1[ROWS*4*DD];
__device__ float g_ff2[ROWS*4*DD];

// ---------------- helpers ----------------
__device__ __forceinline__ uint32_t packbf(float lo, float hi){
    uint32_t r; asm("cvt.rn.bf16x2.f32 %0, %1, %2;" : "=r"(r) : "f"(hi), "f"(lo));
    return r;
}
__device__ __forceinline__ float fexp(float x){
    float y = x * 1.4426950408889634f;
    y = fminf(fmaxf(y, -120.f), 120.f);
    float r = rintf(y);
    float f = y - r;
    float p = 1.f + f*(0.6931471805599453f + f*(0.2402265069591007f +
              f*(0.05550410866482158f + f*(0.009618129107628477f +
              f*0.0013333558146428443f))));
    return __int_as_float(__float_as_int(p) + (((int)r) << 23));
}
__device__ __forceinline__ void mma16(float (&d)[4], const uint32_t* a, uint32_t b0, uint32_t b1){
    asm volatile("mma.sync.aligned.m16n8k16.row.col.f32.bf16.bf16.f32 "
        "{%0,%1,%2,%3},{%4,%5,%6,%7},{%8,%9},{%0,%1,%2,%3};"
        : "+f"(d[0]),"+f"(d[1]),"+f"(d[2]),"+f"(d[3])
        : "r"(a[0]),"r"(a[1]),"r"(a[2]),"r"(a[3]),"r"(b0),"r"(b1));
}
__device__ __forceinline__ void bfsplit(float x, float y, uint32_t& hi, uint32_t& lo){
    hi = packbf(x, y);
    float e0 = __uint_as_float(hi << 16);
    float e1 = __uint_as_float(hi & 0xffff0000u);
    lo = packbf(x - e0, y - e1);
}

// ---------------- small kernels ----------------
__global__ void zero_absmax_kernel() {
    if (threadIdx.x < 4) g_absmax[threadIdx.x] = 0.f;
}

__global__ void __launch_bounds__(256) rmsnorm_kernel(
    const float* __restrict__ x, const float* __restrict__ w,
    float* __restrict__ out, int slot)
{
    __shared__ float red[256];
    int tid = threadIdx.x;
    size_t row = blockIdx.x;
    float4 xv = ((const float4*)(x + row*DD))[tid];
    float ss = xv.x*xv.x + xv.y*xv.y + xv.z*xv.z + xv.w*xv.w;
    red[tid] = ss;
    __syncthreads();
    #pragma unroll
    for (int s = 128; s > 0; s >>= 1) {
        if (tid < s) red[tid] += red[tid + s];
        __syncthreads();
    }
    float rinv = rsqrtf(red[0] * (1.f/1024.f) + 1e-6f);
    __syncthreads();
    float4 wv = ((const float4*)w)[tid];
    float4 o;
    o.x = wv.x * (xv.x * rinv);
    o.y = wv.y * (xv.y * rinv);
    o.z = wv.z * (xv.z * rinv);
    o.w = wv.w * (xv.w * rinv);
    ((float4*)(out + row*DD))[tid] = o;
    float am = fmaxf(fmaxf(fabsf(o.x), fabsf(o.y)), fmaxf(fabsf(o.z), fabsf(o.w)));
    red[tid] = am;
    __syncthreads();
    #pragma unroll
    for (int s = 128; s > 0; s >>= 1) {
        if (tid < s) red[tid] = fmaxf(red[tid], red[tid + s]);
        __syncthreads();
    }
    if (tid == 0) atomicMax((int*)&g_absmax[slot], __float_as_int(red[0]));
}

// quant codes via reciprocal multiply (one FDIV per thread)
__global__ void __launch_bounds__(256) quant_kernel(
    const float* __restrict__ in, float* __restrict__ out, int slot, int n4)
{
    float scale = g_absmax[slot] * (1.f/127.f) + 1e-8f;
    float qinv = 1.f / scale;
    int stride = gridDim.x * blockDim.x;
    for (int i = blockIdx.x*blockDim.x + threadIdx.x; i < n4; i += stride) {
        float4 v = ((const float4*)in)[i];
        v.x = fminf(fmaxf(rintf(v.x * qinv), -128.f), 127.f);
        v.y = fminf(fmaxf(rintf(v.y * qinv), -128.f), 127.f);
        v.z = fminf(fmaxf(rintf(v.z * qinv), -128.f), 127.f);
        v.w = fminf(fmaxf(rintf(v.w * qinv), -128.f), 127.f);
        ((float4*)out)[i] = v;
    }
}

__global__ void __launch_bounds__(256) gate_kernel(
    float* __restrict__ a, const float* __restrict__ bsrc, int n4, int slot)
{
    __shared__ float red[256];
    float am = 0.f;
    int stride = gridDim.x * blockDim.x;
    for (int i = blockIdx.x*blockDim.x + threadIdx.x; i < n4; i += stride) {
        float4 u = ((const float4*)a)[i];
        float4 v = ((const float4*)bsrc)[i];
        float4 g;
        g.x = u.x / (1.f + fexp(-u.x)) * v.x;
        g.y = u.y / (1.f + fexp(-u.y)) * v.y;
        g.z = u.z / (1.f + fexp(-u.z)) * v.z;
        g.w = u.w / (1.f + fexp(-u.w)) * v.w;
        ((float4*)a)[i] = g;
        am = fmaxf(am, fmaxf(fmaxf(fabsf(g.x), fabsf(g.y)), fmaxf(fabsf(g.z), fabsf(g.w))));
    }
    red[threadIdx.x] = am;
    __syncthreads();
    #pragma unroll
    for (int s = 128; s > 0; s >>= 1) {
        if (threadIdx.x < s) red[threadIdx.x] = fmaxf(red[threadIdx.x], red[threadIdx.x + s]);
        __syncthreads();
    }
    if (threadIdx.x == 0) atomicMax((int*)&g_absmax[slot], __float_as_int(red[0]));
}

__global__ void __launch_bounds__(256) conv_combine_kernel(
    const float* __restrict__ x, const float* __restrict__ hrec,
    const float* __restrict__ hattn, const float* __restrict__ nx,
    const float* __restrict__ conv_w, const float* __restrict__ conv_b,
    float* __restrict__ xout)
{
    int bs = blockIdx.x;
    int b = bs >> 11;
    int s = bs & 2047;
    size_t rowbase = (size_t)bs * DD;
    for (int d = threadIdx.x; d < DD; d += 256) {
        float acc = conv_b[d];
        #pragma unroll
        for (int t = 0; t < 5; t++) {
            int ssi = s + t - 2;
            if (ssi >= 0 && ssi < SQ)
                acc = fmaf(nx[((size_t)b*SQ + ssi)*DD + d], conv_w[d*5 + t], acc);
        }
        size_t idx = rowbase + d;
        xout[idx] = x[idx] + hrec[idx] + hattn[idx] + acc;
    }
}

#define KC 32
#define SROWQ 20
#define TILEQ (128*SROWQ)   /* 2560 b32 units per tile */

// ================= bf16x3 GEMM, fp32 A & W (qkv, out-proj): 256 thr =================
__global__ void __launch_bounds__(256) mma_gemm_b3(
    const float* __restrict__ A, const float* __restrict__ W,
    const float* __restrict__ bias, float* __restrict__ C,
    int M, int N, int K)
{
    extern __shared__ uint32_t smem_u[];
    const int NT = 4;

    int tid = threadIdx.x;
    int wid = tid >> 5, lane = tid & 31;
    int wm = (wid & 1) * 64;
    int wn = (wid >> 1) * 32;
    int m0 = blockIdx.y * 128, n0 = blockIdx.x * 128;
    int lrow = tid >> 3, lc4 = (tid & 7) * 4;
    int g = lane >> 2, t4 = lane & 3;

    float d[4][4][4];
    #pragma unroll
    for (int i = 0; i < 4; i++)
        #pragma unroll
        for (int j = 0; j < 4; j++)
            #pragma unroll
            for (int q = 0; q < 4; q++) d[i][j][q] = 0.f;

    float4 av[4], wv[4];
    auto LDG = [&](int t){
        int k0 = t*KC + lc4;
        #pragma unroll
        for (int h = 0; h < 4; h++) {
            av[h] = *(const float4*)(A + (size_t)(m0 + lrow + h*32)*K + k0);
            wv[h] = *(const float4*)(W + (size_t)(n0 + lrow + h*32)*K + k0);
        }
    };
    auto STS = [&](int s){
        uint32_t* bufAh = smem_u + (size_t)s*NT*TILEQ;
        uint32_t* bufAl = bufAh + TILEQ;
        uint32_t* bufBh = bufAh + 2*TILEQ;
        uint32_t* bufBl = bufBh + TILEQ;
        #pragma unroll
        for (int h = 0; h < 4; h++) {
            int u0 = (lrow + h*32)*SROWQ + (tid & 7)*2;
            uint32_t h0, l0, h1, l1;
            bfsplit(av[h].x, av[h].y, h0, l0);
            bfsplit(av[h].z, av[h].w, h1, l1);
            bufAh[u0] = h0; bufAh[u0 + 1] = h1;
            bufAl[u0] = l0; bufAl[u0 + 1] = l1;
            bfsplit(wv[h].x, wv[h].y, h0, l0);
            bfsplit(wv[h].z, wv[h].w, h1, l1);
            bufBh[u0] = h0; bufBh[u0 + 1] = h1;
            bufBl[u0] = l0; bufBl[u0 + 1] = l1;
        }
    };

    const int T = K / KC;
    LDG(0); STS(0);
    if (T > 1) LDG(1);
    __syncthreads();

    for (int t = 0; t < T; t++) {
        const uint32_t* buf = smem_u + (size_t)(t & 1)*NT*TILEQ;
        const uint32_t* Ah  = buf;
        const uint32_t* Al  = buf + TILEQ;
        const uint32_t* Bh  = buf + 2*TILEQ;
        const uint32_t* Bl  = buf + 3*TILEQ;

        #pragma unroll
        for (int ks = 0; ks < 2; ks++) {
            int ku = ks*8;
            uint32_t ah[4][4], al[4][4];
            #pragma unroll
            for (int i = 0; i < 4; i++) {
                const uint32_t* base = Ah + (wm + i*16 + g)*SROWQ + ku + t4;
                ah[i][0] = base[0];
                ah[i][1] = base[8*SROWQ];
                ah[i][2] = base[4];
                ah[i][3] = base[8*SROWQ + 4];
                const uint32_t* b2 = Al + (wm + i*16 + g)*SROWQ + ku + t4;
                al[i][0] = b2[0];
                al[i][1] = b2[8*SROWQ];
                al[i][2] = b2[4];
                al[i][3] = b2[8*SROWQ + 4];
            }
            uint32_t bh[4][2], bl[4][2];
            #pragma unroll
            for (int j = 0; j < 4; j++) {
                const uint32_t* bb = Bh + (wn + j*8 + g)*SROWQ + ku + t4;
                bh[j][0] = bb[0]; bh[j][1] = bb[4];
                const uint32_t* bb2 = Bl + (wn + j*8 + g)*SROWQ + ku + t4;
                bl[j][0] = bb2[0]; bl[j][1] = bb2[4];
            }
            #pragma unroll
            for (int i = 0; i < 4; i++)
                #pragma unroll
                for (int j = 0; j < 4; j++) {
                    mma16(d[i][j], ah[i], bh[j][0], bh[j][1]);
                    mma16(d[i][j], al[i], bh[j][0], bh[j][1]);
                    mma16(d[i][j], ah[i], bl[j][0], bl[j][1]);
                }
        }

        if (t + 1 < T) {
            STS((t + 1) & 1);
            if (t + 2 < T) LDG(t + 2);
        }
        __syncthreads();
    }

    int r = lane >> 2, c2 = (lane & 3) * 2;
    #pragma unroll
    for (int j = 0; j < 4; j++) {
        int cc = n0 + wn + j*8 + c2;
        float b0 = bias[cc], b1 = bias[cc + 1];
        #pragma unroll
        for (int i = 0; i < 4; i++) {
            int r0 = m0 + wm + i*16 + r;
            #pragma unroll
            for (int half = 0; half < 2; half++) {
                int rr = r0 + half*8;
                size_t idx = (size_t)rr*N + cc;
                float2 o;
                o.x = d[i][j][half*2 + 0] + b0;
                o.y = d[i][j][half*2 + 1] + b1;
                *(float2*)(C + idx) = o;
            }
        }
    }
}

// ================= bf16x2 GEMM body (fp32 code A), shared by q and w12 =================
template<int EPI>
__device__ __forceinline__ void gemm_q_body(
    const float* __restrict__ A, const float* __restrict__ W,
    const float* __restrict__ bias, float* __restrict__ C,
    int N, int K, int m0, int n0,
    const float* __restrict__ e1, const float* __restrict__ e2, int slot,
    uint32_t* smem_u)
{
    const int NT = 3;
    int tid = threadIdx.x;
    int wid = tid >> 5, lane = tid & 31;
    int wm = (wid & 1) * 64;
    int wn = (wid >> 1) * 32;
    int lrow = tid >> 3, lc4 = (tid & 7) * 4;
    int g = lane >> 2, t4 = lane & 3;

    float d[4][4][4];
    #pragma unroll
    for (int i = 0; i < 4; i++)
        #pragma unroll
        for (int j = 0; j < 4; j++)
            #pragma unroll
            for (int q = 0; q < 4; q++) d[i][j][q] = 0.f;

    float4 av[4], wv[4];
    auto LDG = [&](int t){
        int k0 = t*KC + lc4;
        #pragma unroll
        for (int h = 0; h < 4; h++) {
            av[h] = *(const float4*)(A + (size_t)(m0 + lrow + h*32)*K + k0);
            wv[h] = *(const float4*)(W + (size_t)(n0 + lrow + h*32)*K + k0);
        }
    };
    auto STS = [&](int s){
        uint32_t* bufAh = smem_u + (size_t)s*NT*TILEQ;
        uint32_t* bufBh = bufAh + TILEQ;
        uint32_t* bufBl = bufBh + TILEQ;
        #pragma unroll
        for (int h = 0; h < 4; h++) {
            int u0 = (lrow + h*32)*SROWQ + (tid & 7)*2;
            bufAh[u0]     = packbf(av[h].x, av[h].y);
            bufAh[u0 + 1] = packbf(av[h].z, av[h].w);
            uint32_t h0, l0, h1, l1;
            bfsplit(wv[h].x, wv[h].y, h0, l0);
            bfsplit(wv[h].z, wv[h].w, h1, l1);
            bufBh[u0] = h0; bufBh[u0 + 1] = h1;
            bufBl[u0] = l0; bufBl[u0 + 1] = l1;
        }
    };

    const int T = K / KC;
    LDG(0); STS(0);
    if (T > 1) LDG(1);
    __syncthreads();

    for (int t = 0; t < T; t++) {
        const uint32_t* buf = smem_u + (size_t)(t & 1)*NT*TILEQ;
        const uint32_t* Ah  = buf;
        const uint32_t* Bh  = buf + TILEQ;
        const uint32_t* Bl  = buf + 2*TILEQ;

        #pragma unroll
        for (int ks = 0; ks < 2; ks++) {
            int ku = ks*8;
            uint32_t ah[4][4];
            #pragma unroll
            for (int i = 0; i < 4; i++) {
                const uint32_t* base = Ah + (wm + i*16 + g)*SROWQ + ku + t4;
                ah[i][0] = base[0];
                ah[i][1] = base[8*SROWQ];
                ah[i][2] = base[4];
                ah[i][3] = base[8*SROWQ + 4];
            }
            uint32_t bh[4][2], bl[4][2];
            #pragma unroll
            for (int j = 0; j < 4; j++) {
                const uint32_t* bb = Bh + (wn + j*8 + g)*SROWQ + ku + t4;
                bh[j][0] = bb[0]; bh[j][1] = bb[4];
                const uint32_t* bb2 = Bl + (wn + j*8 + g)*SROWQ + ku + t4;
                bl[j][0] = bb2[0]; bl[j][1] = bb2[4];
            }
            #pragma unroll
            for (int i = 0; i < 4; i++)
                #pragma unroll
                for (int j = 0; j < 4; j++) {
                    mma16(d[i][j], ah[i], bh[j][0], bh[j][1]);
                    mma16(d[i][j], ah[i], bl[j][0], bl[j][1]);
                }
        }

        if (t + 1 < T) {
            STS((t + 1) & 1);
            if (t + 2 < T) LDG(t + 2);
        }
        __syncthreads();
    }

    float alpha = g_absmax[slot] * (1.f/127.f) + 1e-8f;
    int r = lane >> 2, c2 = (lane & 3) * 2;

    #pragma unroll
    for (int j = 0; j < 4; j++) {
        int cc = n0 + wn + j*8 + c2;
        float b0 = bias[cc], b1 = bias[cc + 1];
        float dn0 = 0.f, dn1 = 0.f;
        if (EPI == 1) { dn0 = expf(e2[cc]); dn1 = expf(e2[cc + 1]); }
        #pragma unroll
        for (int i = 0; i < 4; i++) {
            int r0 = m0 + wm + i*16 + r;
            #pragma unroll
            for (int half = 0; half < 2; half++) {
                int rr = r0 + half*8;
                size_t idx = (size_t)rr*N + cc;
                float v0 = alpha * d[i][j][half*2 + 0] + b0;
                float v1 = alpha * d[i][j][half*2 + 1] + b1;
                if (EPI == 1) {
                    v0 = tanhf(v0 + dn0 * e1[idx]);
                    v1 = tanhf(v1 + dn1 * e1[idx + 1]);
                } else if (EPI == 2) {
                    v0 += e1[idx];
                    v1 += e1[idx + 1];
                }
                float2 o; o.x = v0; o.y = v1;
                *(float2*)(C + idx) = o;
            }
        }
    }
}

template<int EPI>
__global__ void __launch_bounds__(256, 2) mma_gemm_q(
    const float* __restrict__ A, const float* __restrict__ W,
    const float* __restrict__ bias, float* __restrict__ C,
    int M, int N, int K,
    const float* __restrict__ e1, const float* __restrict__ e2, int slot)
{
    extern __shared__ uint32_t smem_u[];
    gemm_q_body<EPI>(A, W, bias, C, N, K,
                     blockIdx.y * 128, blockIdx.x * 128, e1, e2, slot, smem_u);
}

// merged w1+w2: blockIdx.x < 32 -> (W1, C1); else (W2, C2)
__global__ void __launch_bounds__(256, 2) mma_gemm_w12(
    const float* __restrict__ A,
    const float* __restrict__ W1, const float* __restrict__ W2,
    const float* __restrict__ b1, const float* __restrict__ b2,
    float* __restrict__ C1, float* __restrict__ C2,
    int N, int K, int slot)
{
    extern __shared__ uint32_t smem_u[];
    bool first = blockIdx.x < 32;
    gemm_q_body<0>(A, first ? W1 : W2, first ? b1 : b2, first ? C1 : C2,
                   N, K, blockIdx.y * 128, (blockIdx.x & 31) * 128,
                   nullptr, nullptr, slot, smem_u);
}

// ================= MMA flash attention (all-bf16x3, register-resident P) =================
#define SKB 36
#define SVT 36
#define SVS 68
#define OFF_KBL  2304
#define OFF_VTH  4608
#define OFF_VTL  6912
#define OFF_VST  9216
#define ATTN_SMEM (13568*4)

__global__ void __launch_bounds__(256, 2) attn_mma(
    const float* __restrict__ qkv, float* __restrict__ out)
{
    extern __shared__ uint32_t smem_a[];
    uint32_t* Kbh  = smem_a;
    uint32_t* Kbl  = smem_a + OFF_KBL;
    uint32_t* VThi = smem_a + OFF_VTH;
    uint32_t* VTlo = smem_a + OFF_VTL;
    float*    Vst  = (float*)(smem_a + OFF_VST);

    int tid = threadIdx.x, w = tid >> 5, lane = tid & 31;
    int g = lane >> 2, t = lane & 3;
    int q0 = blockIdx.x * 128, h = blockIdx.y, b = blockIdx.z;
    const float* base = qkv + (size_t)b*SQ*3072 + h*64;

    uint32_t qh[4][4], ql[4][4];
    {
        const float* Qb = base + (size_t)(q0 + w*16)*3072;
        #pragma unroll
        for (int ks = 0; ks < 4; ks++) {
            #pragma unroll
            for (int q = 0; q < 4; q++) {
                int row = (q & 1) ? (g + 8) : g;
                int col = ks*16 + 2*t + ((q & 2) ? 8 : 0);
                float2 v = *(const float2*)(Qb + (size_t)row*3072 + col);
                v.x *= 0.125f; v.y *= 0.125f;
                bfsplit(v.x, v.y, qh[ks][q], ql[ks][q]);
            }
        }
    }

    float o[8][4];
    #pragma unroll
    for (int j = 0; j < 8; j++)
        #pragma unroll
        for (int q = 0; q < 4; q++) o[j][q] = 0.f;
    float m0 = -1e30f, m1 = -1e30f, l0 = 0.f, l1 = 0.f;

    for (int kt = 0; kt < SQ/64; kt++) {
        __syncthreads();
        for (int i = tid; i < 1024; i += 256) {
            int row = i >> 4, c4 = (i & 15) * 4;
            const float* gp = base + (size_t)(kt*64 + row)*3072 + 1024 + c4;
            float4 kv = *(const float4*)gp;
            float4 vv = *(const float4*)(gp + 1024);
            uint32_t h0, lo0, h1, lo1;
            bfsplit(kv.x, kv.y, h0, lo0);
            bfsplit(kv.z, kv.w, h1, lo1);
            int u = row*SKB + (i & 15)*2;
            Kbh[u] = h0; Kbh[u + 1] = h1;
            Kbl[u] = lo0; Kbl[u + 1] = lo1;
            *(float4*)(Vst + row*SVS + c4) = vv;
        }
        __syncthreads();
        for (int i = tid; i < 1024; i += 256) {
            int kp = i & 31, dp = i >> 5;
            float2 v0 = *(const float2*)(Vst + (2*kp)*SVS + 2*dp);
            float2 v1 = *(const float2*)(Vst + (2*kp + 1)*SVS + 2*dp);
            uint32_t h0, l0x, h1, l1x;
            bfsplit(v0.x, v1.x, h0, l0x);
            bfsplit(v0.y, v1.y, h1, l1x);
            VThi[(2*dp)*SVT + kp]     = h0;
            VTlo[(2*dp)*SVT + kp]     = l0x;
            VThi[(2*dp + 1)*SVT + kp] = h1;
            VTlo[(2*dp + 1)*SVT + kp] = l1x;
        }
        __syncthreads();

        float s[8][4];
        #pragma unroll
        for (int j = 0; j < 8; j++)
            #pragma unroll
            for (int q = 0; q < 4; q++) s[j][q] = 0.f;

        #pragma unroll
        for (int j = 0; j < 8; j++) {
            #pragma unroll
            for (int ks = 0; ks < 4; ks++) {
                const uint32_t* kb  = Kbh + (j*8 + g)*SKB + ks*8 + t;
                const uint32_t* kb2 = Kbl + (j*8 + g)*SKB + ks*8 + t;
                uint32_t bh0 = kb[0],  bh1 = kb[4];
                uint32_t bl0 = kb2[0], bl1 = kb2[4];
                mma16(s[j], qh[ks], bh0, bh1);
                mma16(s[j], ql[ks], bh0, bh1);
                mma16(s[j], qh[ks], bl0, bl1);
            }
        }

        float mt0 = -1e30f, mt1 = -1e30f;
        #pragma unroll
        for (int j = 0; j < 8; j++) {
            mt0 = fmaxf(mt0, fmaxf(s[j][0], s[j][1]));
            mt1 = fmaxf(mt1, fmaxf(s[j][2], s[j][3]));
        }
        mt0 = fmaxf(mt0, __shfl_xor_sync(0xffffffffu, mt0, 1));
        mt0 = fmaxf(mt0, __shfl_xor_sync(0xffffffffu, mt0, 2));
        mt1 = fmaxf(mt1, __shfl_xor_sync(0xffffffffu, mt1, 1));
        mt1 = fmaxf(mt1, __shfl_xor_sync(0xffffffffu, mt1, 2));
        float m0n = fmaxf(m0, mt0), m1n = fmaxf(m1, mt1);
        float a0 = fexp(m0 - m0n), a1 = fexp(m1 - m1n);

        float rs0 = 0.f, rs1 = 0.f;
        #pragma unroll
        for (int j = 0; j < 8; j++) {
            s[j][0] = fexp(s[j][0] - m0n);
            s[j][1] = fexp(s[j][1] - m0n);
            s[j][2] = fexp(s[j][2] - m1n);
            s[j][3] = fexp(s[j][3] - m1n);
            rs0 += s[j][0] + s[j][1];
            rs1 += s[j][2] + s[j][3];
        }
        rs0 += __shfl_xor_sync(0xffffffffu, rs0, 1);
        rs0 += __shfl_xor_sync(0xffffffffu, rs0, 2);
        rs1 += __shfl_xor_sync(0xffffffffu, rs1, 1);
        rs1 += __shfl_xor_sync(0xffffffffu, rs1, 2);
        l0 = l0*a0 + rs0;
        l1 = l1*a1 + rs1;
        m0 = m0n; m1 = m1n;
        #pragma unroll
        for (int j = 0; j < 8; j++) {
            o[j][0] *= a0; o[j][1] *= a0; o[j][2] *= a1; o[j][3] *= a1;
        }

        #pragma unroll
        for (int kk = 0; kk < 4; kk++) {
            uint32_t ah[4], al[4];
            bfsplit(s[2*kk][0],     s[2*kk][1],     ah[0], al[0]);
            bfsplit(s[2*kk][2],     s[2*kk][3],     ah[1], al[1]);
            bfsplit(s[2*kk + 1][0], s[2*kk + 1][1], ah[2], al[2]);
            bfsplit(s[2*kk + 1][2], s[2*kk + 1][3], ah[3], al[3]);
            #pragma unroll
            for (int j = 0; j < 8; j++) {
                const uint32_t* vh = VThi + (j*8 + g)*SVT + kk*8 + t;
                const uint32_t* vl = VTlo + (j*8 + g)*SVT + kk*8 + t;
                uint32_t bh0 = vh[0], bh1 = vh[4];
                uint32_t bl0 = vl[0], bl1 = vl[4];
                mma16(o[j], ah, bh0, bh1);
                mma16(o[j], al, bh0, bh1);
                mma16(o[j], ah, bl0, bl1);
            }
        }
    }

    float inv0 = 1.f / l0, inv1 = 1.f / l1;
    int row0 = q0 + w*16 + g;
    #pragma unroll
    for (int j = 0; j < 8; j++) {
        int col = h*64 + j*8 + 2*t;
        *(float2*)(out + (size_t)(b*SQ + row0)*DD + col) =
            make_float2(o[j][0]*inv0, o[j][1]*inv0);
        *(float2*)(out + (size_t)(b*SQ + row0 + 8)*DD + col) =
            make_float2(o[j][2]*inv1, o[j][3]*inv1);
    }
}

// ---------------- launch ----------------
extern "C" void kernel_launch(void* const* d_in, const int* in_sizes, int n_in,
                              void* d_out, int out_size)
{
    const float* x         = (const float*)d_in[0];
    const float* h_prev    = (const float*)d_in[1];
    const float* norm1_w   = (const float*)d_in[2];
    const float* norm2_w   = (const float*)d_in[3];
    const float* decay     = (const float*)d_in[4];
    const float* rec_W     = (const float*)d_in[5];
    const float* rec_b     = (const float*)d_in[6];
    const float* in_proj_w = (const float*)d_in[7];
    const float* in_proj_b = (const float*)d_in[8];
    const float* out_w     = (const float*)d_in[9];
    const float* out_b     = (const float*)d_in[10];
    const float* conv_w    = (const float*)d_in[11];
    const float* conv_b    = (const float*)d_in[12];
    const float* w1_W      = (const float*)d_in[13];
    const float* w1_b      = (const float*)d_in[14];
    const float* w2_W      = (const float*)d_in[15];
    const float* w2_b      = (const float*)d_in[16];
    const float* w3_W      = (const float*)d_in[17];
    const float* w3_b      = (const float*)d_in[18];

    float* out_x    = (float*)d_out;
    float* out_hrec = out_x + NELEM;

    float *nx, *nx2, *qkv, *attnpre, *hattn, *xbuf, *ff1, *ff2;
    cudaGetSymbolAddress((void**)&nx,      g_nx);
    cudaGetSymbolAddress((void**)&nx2,     g_nx2);
    cudaGetSymbolAddress((void**)&qkv,     g_qkv);
    cudaGetSymbolAddress((void**)&attnpre, g_attnpre);
    cudaGetSymbolAddress((void**)&hattn,   g_hattn);
    cudaGetSymbolAddress((void**)&xbuf,    g_xbuf);
    cudaGetSymbolAddress((void**)&ff1,     g_ff1);
    cudaGetSymbolAddress((void**)&ff2,     g_ff2);

    const int SMB3 = 2*4*TILEQ*4;   // 81920 B
    const int SMQ  = 2*3*TILEQ*4;   // 61440 B
    cudaFuncSetAttribute(mma_gemm_b3,   cudaFuncAttributeMaxDynamicSharedMemorySize, SMB3);
    cudaFuncSetAttribute(mma_gemm_q<1>, cudaFuncAttributeMaxDynamicSharedMemorySize, SMQ);
    cudaFuncSetAttribute(mma_gemm_q<2>, cudaFuncAttributeMaxDynamicSharedMemorySize, SMQ);
    cudaFuncSetAttribute(mma_gemm_w12,  cudaFuncAttributeMaxDynamicSharedMemorySize, SMQ);
    cudaFuncSetAttribute(attn_mma, cudaFuncAttributeMaxDynamicSharedMemorySize, ATTN_SMEM);

    zero_absmax_kernel<<<1, 32>>>();
    // nx = rmsnorm(x), absmax -> slot 0
    rmsnorm_kernel<<<ROWS, 256>>>(x, norm1_w, nx, 0);
    // quant codes of nx -> nx2
    quant_kernel<<<2048, 256>>>(nx, nx2, 0, NELEM/4);
    // qkv = nx @ in_proj_w^T + b   (bf16x3)
    mma_gemm_b3<<<dim3(24, 64), 256, SMB3>>>(nx, in_proj_w, in_proj_b, qkv,
                                             ROWS, 3072, 1024);
    // h_rec = tanh(scale0*(codes @ rec_W^T) + rec_b + exp(decay)*h_prev)
    mma_gemm_q<1><<<dim3(8, 64), 256, SMQ>>>(nx2, rec_W, rec_b, out_hrec,
                                             ROWS, 1024, 1024, h_prev, decay, 0);
    // flash attention
    attn_mma<<<dim3(16, 16, 4), 256, ATTN_SMEM>>>(qkv, attnpre);
    // out projection (bf16x3)
    mma_gemm_b3<<<dim3(8, 64), 256, SMB3>>>(attnpre, out_w, out_b, hattn,
                                            ROWS, 1024, 1024);
    conv_combine_kernel<<<ROWS, 256>>>(x, out_hrec, hattn, nx, conv_w, conv_b, xbuf);
    // nx2 = rmsnorm(xbuf), absmax -> slot 1; quant codes in place
    rmsnorm_kernel<<<ROWS, 256>>>(xbuf, norm2_w, nx2, 1);
    quant_kernel<<<2048, 256>>>(nx2, nx2, 1, NELEM/4);
    // ff1 = codes @ w1, ff2 = codes @ w2 (merged launch)
    mma_gemm_w12<<<dim3(64, 64), 256, SMQ>>>(nx2, w1_W, w2_W, w1_b, w2_b,
                                             ff1, ff2, 4096, 1024, 1);
    // ff1 = silu(ff1)*ff2, absmax -> slot 2; quant codes in place
    gate_kernel<<<4096, 256>>>(ff1, ff2, (ROWS*4096)/4, 2);
    quant_kernel<<<4096, 256>>>(ff1, ff1, 2, (ROWS*4096)/4);
    // out_x = xbuf + scale2*(codes @ w3^T) + b3
    mma_gemm_q<2><<<dim3(8, 64), 256, SMQ>>>(ff1, w3_W, w3_b, out_x,
                                             ROWS, 1024, 4096, xbuf, nullptr, 2);
}